// round 1
// baseline (speedup 1.0000x reference)
#include <cuda_runtime.h>
#include <cuda_bf16.h>
#include <cstdint>

#define N_NODES 100000
#define DH 128          // feature dim (in = hid = out = 128)
#define NPB 8           // nodes per tile in ln_gemm

// ---------------- scratch (static device globals; no runtime alloc) --------
__device__ float g_agg[(size_t)N_NODES * DH];   // 51.2 MB aggregation buffer
__device__ float g_buf[(size_t)N_NODES * DH];   // 51.2 MB inter-layer buffer

// ---------------- zero the aggregation buffer ------------------------------
__global__ void zero_agg_kernel() {
    size_t i = (size_t)blockIdx.x * blockDim.x + threadIdx.x;   // float4 index
    const size_t total = (size_t)N_NODES * (DH / 4);
    float4 z = make_float4(0.f, 0.f, 0.f, 0.f);
    if (i < total) ((float4*)g_agg)[i] = z;
}

// ---------------- edge scatter: agg[dst] += x[src] -------------------------
// One warp per edge. Lane l moves float4 chunk l (32 chunks * 16B = 512B row).
__global__ void scatter_kernel(const float4* __restrict__ xin, int from_buf,
                               const int* __restrict__ src,
                               const int* __restrict__ dst, int E) {
    int warp = (int)((blockIdx.x * (size_t)blockDim.x + threadIdx.x) >> 5);
    int lane = threadIdx.x & 31;
    if (warp >= E) return;
    int s = __ldg(src + warp);
    int d = __ldg(dst + warp);
    const float4* xp = from_buf ? (const float4*)g_buf : xin;
    float4 v = __ldg(xp + (size_t)s * (DH / 4) + lane);
    float4* ap = (float4*)g_agg + (size_t)d * (DH / 4) + lane;
    asm volatile("red.global.add.v4.f32 [%0], {%1,%2,%3,%4};"
                 :: "l"(ap), "f"(v.x), "f"(v.y), "f"(v.z), "f"(v.w)
                 : "memory");
}

// ---------------- fused LayerNorm + GEMM(128x128) + bias (+ReLU) -----------
// 256 threads: col = t&127, kh = t>>7 (split-K half). W held in registers
// (64 floats/thread). Persistent grid; 8 nodes per tile.
__global__ __launch_bounds__(256, 2)
void ln_gemm_kernel(const float* __restrict__ gamma,
                    const float* __restrict__ beta,
                    const float* __restrict__ W,
                    const float* __restrict__ bias,
                    float* __restrict__ out_param, int out_to_param, int relu) {
    __shared__ __align__(16) float xsh[NPB][DH];
    __shared__ __align__(16) float psum[NPB][DH];
    __shared__ __align__(16) float gsh[DH];
    __shared__ __align__(16) float bsh[DH];

    const int t    = threadIdx.x;
    const int col  = t & 127;
    const int kh   = t >> 7;          // 0 or 1
    const int warp = t >> 5;          // 0..7
    const int lane = t & 31;
    float* out = out_to_param ? out_param : g_buf;

    // W[k][col] for k = kh*64 .. kh*64+63  -> registers
    float wreg[64];
#pragma unroll
    for (int kk = 0; kk < 64; kk++)
        wreg[kk] = __ldg(W + (size_t)(kh * 64 + kk) * DH + col);
    const float bcol = __ldg(bias + col);
    if (t < DH) { gsh[t] = gamma[t]; bsh[t] = beta[t]; }
    __syncthreads();

    const int nTiles = N_NODES / NPB;   // 12500 exact
    for (int tile = blockIdx.x; tile < nTiles; tile += gridDim.x) {
        const int n0 = tile * NPB;

        // ---- LayerNorm: warp w normalizes node n0+w (128 vals, 4/lane) ----
        {
            const int n = n0 + warp;
            float4 v = ((const float4*)(g_agg + (size_t)n * DH))[lane];
            float s  = v.x + v.y + v.z + v.w;
            float sq = v.x*v.x + v.y*v.y + v.z*v.z + v.w*v.w;
#pragma unroll
            for (int o = 16; o; o >>= 1) {
                s  += __shfl_xor_sync(0xFFFFFFFFu, s,  o);
                sq += __shfl_xor_sync(0xFFFFFFFFu, sq, o);
            }
            const float mu   = s * (1.0f / DH);
            const float var  = sq * (1.0f / DH) - mu * mu;
            const float rinv = rsqrtf(var + 1e-5f);
            float4 g4 = ((const float4*)gsh)[lane];
            float4 b4 = ((const float4*)bsh)[lane];
            float4 xn;
            xn.x = (v.x - mu) * rinv * g4.x + b4.x;
            xn.y = (v.y - mu) * rinv * g4.y + b4.y;
            xn.z = (v.z - mu) * rinv * g4.z + b4.z;
            xn.w = (v.w - mu) * rinv * g4.w + b4.w;
            ((float4*)xsh[warp])[lane] = xn;
        }
        __syncthreads();

        // ---- GEMM: acc[nn] = sum_{k in half} xn[k] * W[k][col] ----
        float acc[NPB];
#pragma unroll
        for (int nn = 0; nn < NPB; nn++) acc[nn] = 0.f;
#pragma unroll
        for (int kk4 = 0; kk4 < 16; kk4++) {
#pragma unroll
            for (int nn = 0; nn < NPB; nn++) {
                float4 xq = ((const float4*)xsh[nn])[kh * 16 + kk4];
                acc[nn] = fmaf(xq.x, wreg[kk4 * 4 + 0], acc[nn]);
                acc[nn] = fmaf(xq.y, wreg[kk4 * 4 + 1], acc[nn]);
                acc[nn] = fmaf(xq.z, wreg[kk4 * 4 + 2], acc[nn]);
                acc[nn] = fmaf(xq.w, wreg[kk4 * 4 + 3], acc[nn]);
            }
        }

        // ---- combine split-K halves, bias, relu, store ----
        if (kh) {
#pragma unroll
            for (int nn = 0; nn < NPB; nn++) psum[nn][col] = acc[nn];
        }
        __syncthreads();
        if (!kh) {
#pragma unroll
            for (int nn = 0; nn < NPB; nn++) {
                float r = acc[nn] + psum[nn][col] + bcol;
                if (relu) r = fmaxf(r, 0.f);
                out[(size_t)(n0 + nn) * DH + col] = r;
            }
        }
        __syncthreads();   // protect xsh/psum for next tile
    }
}

// ---------------------------------------------------------------------------
extern "C" void kernel_launch(void* const* d_in, const int* in_sizes, int n_in,
                              void* d_out, int out_size) {
    const float* features = (const float*)d_in[0];
    const int*   src      = (const int*)d_in[1];
    const int*   dst      = (const int*)d_in[2];
    const float* g1 = (const float*)d_in[3];
    const float* be1= (const float*)d_in[4];
    const float* W1 = (const float*)d_in[5];
    const float* b1 = (const float*)d_in[6];
    const float* g2 = (const float*)d_in[7];
    const float* be2= (const float*)d_in[8];
    const float* W2 = (const float*)d_in[9];
    const float* b2 = (const float*)d_in[10];
    const float* g3 = (const float*)d_in[11];
    const float* be3= (const float*)d_in[12];
    const float* W3 = (const float*)d_in[13];
    const float* b3 = (const float*)d_in[14];
    float* out = (float*)d_out;

    const int E = in_sizes[1];

    const int zThreads = 256;
    const int zBlocks  = (N_NODES * (DH / 4) + zThreads - 1) / zThreads;

    const int sThreads = 256;
    const long long sTotal = (long long)E * 32;
    const int sBlocks  = (int)((sTotal + sThreads - 1) / sThreads);

    const int gBlocks = 296;   // ~2 blocks per SM, persistent

    // ---- layer 1 ----
    zero_agg_kernel<<<zBlocks, zThreads>>>();
    scatter_kernel<<<sBlocks, sThreads>>>((const float4*)features, 0, src, dst, E);
    ln_gemm_kernel<<<gBlocks, 256>>>(g1, be1, W1, b1, nullptr, 0, 1);
    // ---- layer 2 ----
    zero_agg_kernel<<<zBlocks, zThreads>>>();
    scatter_kernel<<<sBlocks, sThreads>>>((const float4*)features, 1, src, dst, E);
    ln_gemm_kernel<<<gBlocks, 256>>>(g2, be2, W2, b2, nullptr, 0, 1);
    // ---- layer 3 ----
    zero_agg_kernel<<<zBlocks, zThreads>>>();
    scatter_kernel<<<sBlocks, sThreads>>>((const float4*)features, 1, src, dst, E);
    ln_gemm_kernel<<<gBlocks, 256>>>(g3, be3, W3, b3, out, 1, 0);
}

// round 3
// speedup vs baseline: 1.3478x; 1.3478x over previous
#include <cuda_runtime.h>
#include <cuda_bf16.h>
#include <cstdint>

#define N_NODES 100000
#define DH 128          // feature dim (in = hid = out = 128)
#define NPB 8           // nodes per tile in ln_gemm
#define E_MAX 2000000   // static CSR capacity (E = 1.6M in dataset)

// ---------------- scratch (static device globals; no runtime alloc) --------
__device__ float g_agg[(size_t)N_NODES * DH];   // 51.2 MB aggregation buffer
__device__ float g_buf[(size_t)N_NODES * DH];   // 51.2 MB inter-layer buffer
__device__ int   g_cnt[N_NODES];                // per-dst degree histogram
__device__ int   g_off[N_NODES + 1];            // CSR row offsets
__device__ int   g_cur[N_NODES];                // fill cursors
__device__ int   g_nbr[E_MAX];                  // CSR: src node per slot

// ---------------- CSR build ------------------------------------------------
__global__ void zero_cnt_kernel() {
    int i = blockIdx.x * blockDim.x + threadIdx.x;
    if (i < N_NODES) g_cnt[i] = 0;
}

__global__ void hist_kernel(const int* __restrict__ dst, int E) {
    int e = blockIdx.x * blockDim.x + threadIdx.x;
    if (e < E) atomicAdd(&g_cnt[__ldg(dst + e)], 1);
}

// Single-block exclusive scan over 100k counts (chunk-per-thread + block scan)
__global__ void scan_kernel() {
    __shared__ int part[1024];
    const int t = threadIdx.x;
    const int chunk = (N_NODES + 1023) / 1024;          // 98
    int b = t * chunk;
    int e = min(N_NODES, b + chunk);
    int s = 0;
    for (int i = b; i < e; i++) s += g_cnt[i];
    part[t] = s;
    __syncthreads();
    // Hillis-Steele inclusive scan
    for (int o = 1; o < 1024; o <<= 1) {
        int v = (t >= o) ? part[t - o] : 0;
        __syncthreads();
        part[t] += v;
        __syncthreads();
    }
    int run = (t == 0) ? 0 : part[t - 1];
    for (int i = b; i < e; i++) {
        g_off[i] = run;
        g_cur[i] = run;
        run += g_cnt[i];
    }
    if (e == N_NODES) g_off[N_NODES] = run;   // all tail threads write total
}

__global__ void fill_kernel(const int* __restrict__ src,
                            const int* __restrict__ dst, int E) {
    int e = blockIdx.x * blockDim.x + threadIdx.x;
    if (e < E) {
        int pos = atomicAdd(&g_cur[__ldg(dst + e)], 1);
        g_nbr[pos] = __ldg(src + e);
    }
}

// ---------------- CSR gather aggregation: agg[n] = sum_{s in nbr(n)} x[s] --
// One warp per node; lane l owns float4 chunk l of the 512B row.
__global__ __launch_bounds__(256)
void gather_kernel(const float4* __restrict__ xin, int from_buf) {
    int node = (int)((blockIdx.x * (size_t)blockDim.x + threadIdx.x) >> 5);
    int lane = threadIdx.x & 31;
    if (node >= N_NODES) return;
    const float4* xp = from_buf ? (const float4*)g_buf : xin;
    int i   = __ldg(&g_off[node]);
    int end = __ldg(&g_off[node + 1]);
    float4 acc = make_float4(0.f, 0.f, 0.f, 0.f);
    for (; i + 1 < end; i += 2) {                 // 2 independent loads in flight
        int s0 = __ldg(g_nbr + i);
        int s1 = __ldg(g_nbr + i + 1);
        float4 v0 = __ldg(xp + (size_t)s0 * (DH / 4) + lane);
        float4 v1 = __ldg(xp + (size_t)s1 * (DH / 4) + lane);
        acc.x += v0.x + v1.x;  acc.y += v0.y + v1.y;
        acc.z += v0.z + v1.z;  acc.w += v0.w + v1.w;
    }
    if (i < end) {
        int s0 = __ldg(g_nbr + i);
        float4 v0 = __ldg(xp + (size_t)s0 * (DH / 4) + lane);
        acc.x += v0.x;  acc.y += v0.y;  acc.z += v0.z;  acc.w += v0.w;
    }
    ((float4*)g_agg)[(size_t)node * (DH / 4) + lane] = acc;
}

// ---------------- fused LayerNorm + GEMM(128x128) + bias (+ReLU) -----------
__global__ __launch_bounds__(256, 2)
void ln_gemm_kernel(const float* __restrict__ gamma,
                    const float* __restrict__ beta,
                    const float* __restrict__ W,
                    const float* __restrict__ bias,
                    float* __restrict__ out_param, int out_to_param, int relu) {
    __shared__ __align__(16) float xsh[NPB][DH];
    __shared__ __align__(16) float psum[NPB][DH];
    __shared__ __align__(16) float gsh[DH];
    __shared__ __align__(16) float bsh[DH];

    const int t    = threadIdx.x;
    const int col  = t & 127;
    const int kh   = t >> 7;          // 0 or 1
    const int warp = t >> 5;          // 0..7
    const int lane = t & 31;
    float* out = out_to_param ? out_param : g_buf;

    float wreg[64];
#pragma unroll
    for (int kk = 0; kk < 64; kk++)
        wreg[kk] = __ldg(W + (size_t)(kh * 64 + kk) * DH + col);
    const float bcol = __ldg(bias + col);
    if (t < DH) { gsh[t] = gamma[t]; bsh[t] = beta[t]; }
    __syncthreads();

    const int nTiles = N_NODES / NPB;   // 12500 exact
    for (int tile = blockIdx.x; tile < nTiles; tile += gridDim.x) {
        const int n0 = tile * NPB;

        // ---- LayerNorm: warp w normalizes node n0+w ----
        {
            const int n = n0 + warp;
            float4 v = ((const float4*)(g_agg + (size_t)n * DH))[lane];
            float s  = v.x + v.y + v.z + v.w;
            float sq = v.x*v.x + v.y*v.y + v.z*v.z + v.w*v.w;
#pragma unroll
            for (int o = 16; o; o >>= 1) {
                s  += __shfl_xor_sync(0xFFFFFFFFu, s,  o);
                sq += __shfl_xor_sync(0xFFFFFFFFu, sq, o);
            }
            const float mu   = s * (1.0f / DH);
            const float var  = sq * (1.0f / DH) - mu * mu;
            const float rinv = rsqrtf(var + 1e-5f);
            float4 g4 = ((const float4*)gsh)[lane];
            float4 b4 = ((const float4*)bsh)[lane];
            float4 xn;
            xn.x = (v.x - mu) * rinv * g4.x + b4.x;
            xn.y = (v.y - mu) * rinv * g4.y + b4.y;
            xn.z = (v.z - mu) * rinv * g4.z + b4.z;
            xn.w = (v.w - mu) * rinv * g4.w + b4.w;
            ((float4*)xsh[warp])[lane] = xn;
        }
        __syncthreads();

        // ---- GEMM: acc[nn] = sum_{k in half} xn[k] * W[k][col] ----
        float acc[NPB];
#pragma unroll
        for (int nn = 0; nn < NPB; nn++) acc[nn] = 0.f;
#pragma unroll
        for (int kk4 = 0; kk4 < 16; kk4++) {
#pragma unroll
            for (int nn = 0; nn < NPB; nn++) {
                float4 xq = ((const float4*)xsh[nn])[kh * 16 + kk4];
                acc[nn] = fmaf(xq.x, wreg[kk4 * 4 + 0], acc[nn]);
                acc[nn] = fmaf(xq.y, wreg[kk4 * 4 + 1], acc[nn]);
                acc[nn] = fmaf(xq.z, wreg[kk4 * 4 + 2], acc[nn]);
                acc[nn] = fmaf(xq.w, wreg[kk4 * 4 + 3], acc[nn]);
            }
        }

        // ---- combine split-K halves, bias, relu, store ----
        if (kh) {
#pragma unroll
            for (int nn = 0; nn < NPB; nn++) psum[nn][col] = acc[nn];
        }
        __syncthreads();
        if (!kh) {
#pragma unroll
            for (int nn = 0; nn < NPB; nn++) {
                float r = acc[nn] + psum[nn][col] + bcol;
                if (relu) r = fmaxf(r, 0.f);
                out[(size_t)(n0 + nn) * DH + col] = r;
            }
        }
        __syncthreads();
    }
}

// ---------------------------------------------------------------------------
extern "C" void kernel_launch(void* const* d_in, const int* in_sizes, int n_in,
                              void* d_out, int out_size) {
    const float* features = (const float*)d_in[0];
    const int*   src      = (const int*)d_in[1];
    const int*   dst      = (const int*)d_in[2];
    const float* g1 = (const float*)d_in[3];
    const float* be1= (const float*)d_in[4];
    const float* W1 = (const float*)d_in[5];
    const float* b1 = (const float*)d_in[6];
    const float* g2 = (const float*)d_in[7];
    const float* be2= (const float*)d_in[8];
    const float* W2 = (const float*)d_in[9];
    const float* b2 = (const float*)d_in[10];
    const float* g3 = (const float*)d_in[11];
    const float* be3= (const float*)d_in[12];
    const float* W3 = (const float*)d_in[13];
    const float* b3 = (const float*)d_in[14];
    float* out = (float*)d_out;

    const int E = in_sizes[1];

    // ---- CSR build (once per call, shared by all 3 layers) ----
    zero_cnt_kernel<<<(N_NODES + 255) / 256, 256>>>();
    hist_kernel<<<(E + 255) / 256, 256>>>(dst, E);
    scan_kernel<<<1, 1024>>>();
    fill_kernel<<<(E + 255) / 256, 256>>>(src, dst, E);

    const int gatherBlocks = (N_NODES * 32 + 255) / 256;   // warp per node
    const int gBlocks = 296;

    // ---- layer 1 ----
    gather_kernel<<<gatherBlocks, 256>>>((const float4*)features, 0);
    ln_gemm_kernel<<<gBlocks, 256>>>(g1, be1, W1, b1, nullptr, 0, 1);
    // ---- layer 2 ----
    gather_kernel<<<gatherBlocks, 256>>>((const float4*)features, 1);
    ln_gemm_kernel<<<gBlocks, 256>>>(g2, be2, W2, b2, nullptr, 0, 1);
    // ---- layer 3 ----
    gather_kernel<<<gatherBlocks, 256>>>((const float4*)features, 1);
    ln_gemm_kernel<<<gBlocks, 256>>>(g3, be3, W3, b3, out, 1, 0);
}

// round 5
// speedup vs baseline: 1.4719x; 1.0920x over previous
#include <cuda_runtime.h>
#include <cuda_bf16.h>
#include <cstdint>

#define N_NODES 100000
#define DH 128          // feature dim (in = hid = out = 128)
#define NPB 8           // nodes per tile in gemm
#define E_MAX 2000000   // static CSR capacity (E = 1.6M in dataset)

// ---- packed f32x2 helpers (SASS FFMA2; PTX-only path) ----------------------
#define PACK2(d, lo, hi) \
    asm("mov.b64 %0, {%1, %2};" : "=l"(d) : "f"(lo), "f"(hi))
#define UNPACK2(lo, hi, v) \
    asm("mov.b64 {%0, %1}, %2;" : "=f"(lo), "=f"(hi) : "l"(v))
#define FMA2(d, a, b, c) \
    asm("fma.rn.f32x2 %0, %1, %2, %3;" : "=l"(d) : "l"(a), "l"(b), "l"(c))

// ---------------- scratch (static device globals; no runtime alloc) --------
__device__ float g_agg[(size_t)N_NODES * DH];   // LN'd aggregation (input to GEMM)
__device__ float g_buf[(size_t)N_NODES * DH];   // inter-layer activations
__device__ int   g_cnt[N_NODES];
__device__ int   g_off[N_NODES + 1];
__device__ int   g_cur[N_NODES];
__device__ int   g_nbr[E_MAX];

// ---------------- CSR build ------------------------------------------------
__global__ void zero_cnt_kernel() {
    int i = blockIdx.x * blockDim.x + threadIdx.x;
    if (i < N_NODES) g_cnt[i] = 0;
}

__global__ void hist_kernel(const int* __restrict__ dst, int E) {
    int e = blockIdx.x * blockDim.x + threadIdx.x;
    if (e < E) atomicAdd(&g_cnt[__ldg(dst + e)], 1);
}

__global__ void scan_kernel() {
    __shared__ int part[1024];
    const int t = threadIdx.x;
    const int chunk = (N_NODES + 1023) / 1024;
    int b = t * chunk;
    int e = min(N_NODES, b + chunk);
    int s = 0;
    for (int i = b; i < e; i++) s += g_cnt[i];
    part[t] = s;
    __syncthreads();
    for (int o = 1; o < 1024; o <<= 1) {
        int v = (t >= o) ? part[t - o] : 0;
        __syncthreads();
        part[t] += v;
        __syncthreads();
    }
    int run = (t == 0) ? 0 : part[t - 1];
    for (int i = b; i < e; i++) {
        g_off[i] = run;
        g_cur[i] = run;
        run += g_cnt[i];
    }
    if (e == N_NODES) g_off[N_NODES] = run;
}

__global__ void fill_kernel(const int* __restrict__ src,
                            const int* __restrict__ dst, int E) {
    int e = blockIdx.x * blockDim.x + threadIdx.x;
    if (e < E) {
        int pos = atomicAdd(&g_cur[__ldg(dst + e)], 1);
        g_nbr[pos] = __ldg(src + e);
    }
}

// ------ CSR gather + fused LayerNorm: g_agg[n] = LN(sum_{s in nbr(n)} x[s]) -
// One warp per node; lane l owns float4 chunk l of the 512B row.
__global__ __launch_bounds__(256)
void gather_ln_kernel(const float4* __restrict__ xin, int from_buf,
                      const float* __restrict__ gamma,
                      const float* __restrict__ beta) {
    int node = (int)((blockIdx.x * (size_t)blockDim.x + threadIdx.x) >> 5);
    int lane = threadIdx.x & 31;
    if (node >= N_NODES) return;
    const float4* xp = from_buf ? (const float4*)g_buf : xin;
    int i   = __ldg(&g_off[node]);
    int end = __ldg(&g_off[node + 1]);
    float4 acc = make_float4(0.f, 0.f, 0.f, 0.f);
    for (; i + 1 < end; i += 2) {
        int s0 = __ldg(g_nbr + i);
        int s1 = __ldg(g_nbr + i + 1);
        float4 v0 = __ldg(xp + (size_t)s0 * (DH / 4) + lane);
        float4 v1 = __ldg(xp + (size_t)s1 * (DH / 4) + lane);
        acc.x += v0.x + v1.x;  acc.y += v0.y + v1.y;
        acc.z += v0.z + v1.z;  acc.w += v0.w + v1.w;
    }
    if (i < end) {
        int s0 = __ldg(g_nbr + i);
        float4 v0 = __ldg(xp + (size_t)s0 * (DH / 4) + lane);
        acc.x += v0.x;  acc.y += v0.y;  acc.z += v0.z;  acc.w += v0.w;
    }
    // ---- LayerNorm over the row held by this warp ----
    float s  = acc.x + acc.y + acc.z + acc.w;
    float sq = acc.x*acc.x + acc.y*acc.y + acc.z*acc.z + acc.w*acc.w;
#pragma unroll
    for (int o = 16; o; o >>= 1) {
        s  += __shfl_xor_sync(0xFFFFFFFFu, s,  o);
        sq += __shfl_xor_sync(0xFFFFFFFFu, sq, o);
    }
    const float mu   = s * (1.0f / DH);
    const float var  = sq * (1.0f / DH) - mu * mu;
    const float rinv = rsqrtf(var + 1e-5f);
    float4 g4 = __ldg((const float4*)gamma + lane);
    float4 b4 = __ldg((const float4*)beta  + lane);
    float4 xn;
    xn.x = (acc.x - mu) * rinv * g4.x + b4.x;
    xn.y = (acc.y - mu) * rinv * g4.y + b4.y;
    xn.z = (acc.z - mu) * rinv * g4.z + b4.z;
    xn.w = (acc.w - mu) * rinv * g4.w + b4.w;
    ((float4*)g_agg)[(size_t)node * (DH / 4) + lane] = xn;
}

// ---------------- pure GEMM(100000x128 @ 128x128) + bias (+ReLU) -----------
// 256 threads = 8 K-groups (warp == K-group, 16 k each) x 32 col-groups
// (4 contiguous cols/thread as two f32x2 W pairs in registers).
// x tile staged in shared PRE-DUPLICATED as (x,x) f32x2 so one broadcast
// LDS.64 feeds two FFMA2. Split-K reduced through a shared staging buffer.
__global__ __launch_bounds__(256, 2)
void gemm_kernel(const float* __restrict__ W,
                 const float* __restrict__ bias,
                 float* __restrict__ out_param, int out_to_param, int relu) {
    __shared__ __align__(16) unsigned long long xdup[2][NPB][DH];  // 16 KB
    __shared__ __align__(16) float4 red4[8 * NPB * 32];            // 32 KB

    const int t  = threadIdx.x;
    const int kg = t >> 5;      // warp index == K-group (0..7)
    const int cg = t & 31;      // col group: cols cg*4 .. cg*4+3
    float* out = out_to_param ? out_param : g_buf;

    // W registers: two f32x2 pairs per k (16 k in this group)
    unsigned long long w01[16], w23[16];
#pragma unroll
    for (int kk = 0; kk < 16; kk++) {
        const float4 w4 = __ldg((const float4*)(W + (size_t)(kg * 16 + kk) * DH) + cg);
        PACK2(w01[kk], w4.x, w4.y);
        PACK2(w23[kk], w4.z, w4.w);
    }
    const float4 bias4 = __ldg((const float4*)bias + cg);

    // loader mapping: thread loads float4 of node (t>>5), word quad (t&31)
    const int nn_l = t >> 5;
    const int kq_l = t & 31;

    const int nTiles = N_NODES / NPB;       // 12500 exact
    int tile = blockIdx.x;
    float4 nxt = make_float4(0.f, 0.f, 0.f, 0.f);
    if (tile < nTiles)
        nxt = __ldg((const float4*)g_agg + (size_t)(tile * NPB + nn_l) * (DH / 4) + kq_l);

    int buf = 0;
    for (; tile < nTiles; tile += gridDim.x, buf ^= 1) {
        const int n0 = tile * NPB;

        // stage current tile (duplicated pairs), 2x STS.128 per thread
        {
            unsigned long long p0, p1, p2, p3;
            PACK2(p0, nxt.x, nxt.x);
            PACK2(p1, nxt.y, nxt.y);
            PACK2(p2, nxt.z, nxt.z);
            PACK2(p3, nxt.w, nxt.w);
            ulonglong2* xd = (ulonglong2*)&xdup[buf][nn_l][kq_l * 4];
            xd[0] = make_ulonglong2(p0, p1);
            xd[1] = make_ulonglong2(p2, p3);
        }
        __syncthreads();

        // prefetch next tile into registers (overlaps compute)
        const int tile2 = tile + gridDim.x;
        if (tile2 < nTiles)
            nxt = __ldg((const float4*)g_agg + (size_t)(tile2 * NPB + nn_l) * (DH / 4) + kq_l);

        // ---- compute: acc[nn] over this warp's 16 k values ----
        unsigned long long acc01[NPB], acc23[NPB];
        unsigned long long zero; PACK2(zero, 0.f, 0.f);
#pragma unroll
        for (int nn = 0; nn < NPB; nn++) { acc01[nn] = zero; acc23[nn] = zero; }

        const unsigned long long* xb = &xdup[buf][0][kg * 16];
#pragma unroll
        for (int kk = 0; kk < 16; kk++) {
            const unsigned long long a = w01[kk];
            const unsigned long long b = w23[kk];
#pragma unroll
            for (int nn = 0; nn < NPB; nn++) {
                const unsigned long long x2 = xb[nn * DH + kk];   // LDS.64 broadcast
                FMA2(acc01[nn], x2, a, acc01[nn]);
                FMA2(acc23[nn], x2, b, acc23[nn]);
            }
        }

        // ---- stage partials: red4[kg][nn][cg] ----
#pragma unroll
        for (int nn = 0; nn < NPB; nn++) {
            float a0, a1, a2, a3;
            UNPACK2(a0, a1, acc01[nn]);
            UNPACK2(a2, a3, acc23[nn]);
            red4[kg * (NPB * 32) + nn * 32 + cg] = make_float4(a0, a1, a2, a3);
        }
        __syncthreads();

        // ---- reduce over 8 K-groups: thread t owns output float4 #t ----
        {
            float4 sv = red4[t];
#pragma unroll
            for (int g = 1; g < 8; g++) {
                float4 r = red4[g * (NPB * 32) + t];
                sv.x += r.x; sv.y += r.y; sv.z += r.z; sv.w += r.w;
            }
            sv.x += bias4.x; sv.y += bias4.y; sv.z += bias4.z; sv.w += bias4.w;
            if (relu) {
                sv.x = fmaxf(sv.x, 0.f); sv.y = fmaxf(sv.y, 0.f);
                sv.z = fmaxf(sv.z, 0.f); sv.w = fmaxf(sv.w, 0.f);
            }
            // NB: reduce-phase bias column = (t&31), same mapping as compute cg
            ((float4*)out)[(size_t)(n0 + (t >> 5)) * (DH / 4) + (t & 31)] = sv;
        }
        // next iteration's first __syncthreads() orders red4 reuse
    }
}

// ---------------------------------------------------------------------------
extern "C" void kernel_launch(void* const* d_in, const int* in_sizes, int n_in,
                              void* d_out, int out_size) {
    const float* features = (const float*)d_in[0];
    const int*   src      = (const int*)d_in[1];
    const int*   dst      = (const int*)d_in[2];
    const float* g1 = (const float*)d_in[3];
    const float* be1= (const float*)d_in[4];
    const float* W1 = (const float*)d_in[5];
    const float* b1 = (const float*)d_in[6];
    const float* g2 = (const float*)d_in[7];
    const float* be2= (const float*)d_in[8];
    const float* W2 = (const float*)d_in[9];
    const float* b2 = (const float*)d_in[10];
    const float* g3 = (const float*)d_in[11];
    const float* be3= (const float*)d_in[12];
    const float* W3 = (const float*)d_in[13];
    const float* b3 = (const float*)d_in[14];
    float* out = (float*)d_out;

    const int E = in_sizes[1];

    // ---- CSR build (once per call, shared by all 3 layers) ----
    zero_cnt_kernel<<<(N_NODES + 255) / 256, 256>>>();
    hist_kernel<<<(E + 255) / 256, 256>>>(dst, E);
    scan_kernel<<<1, 1024>>>();
    fill_kernel<<<(E + 255) / 256, 256>>>(src, dst, E);

    const int gatherBlocks = (N_NODES * 32 + 255) / 256;   // warp per node
    const int gBlocks = 296;                               // persistent GEMM grid

    // ---- layer 1 ----
    gather_ln_kernel<<<gatherBlocks, 256>>>((const float4*)features, 0, g1, be1);
    gemm_kernel<<<gBlocks, 256>>>(W1, b1, nullptr, 0, 1);
    // ---- layer 2 ----
    gather_ln_kernel<<<gatherBlocks, 256>>>((const float4*)features, 1, g2, be2);
    gemm_kernel<<<gBlocks, 256>>>(W2, b2, nullptr, 0, 1);
    // ---- layer 3 ----
    gather_ln_kernel<<<gatherBlocks, 256>>>((const float4*)features, 1, g3, be3);
    gemm_kernel<<<gBlocks, 256>>>(W3, b3, out, 1, 0);
}

// round 9
// speedup vs baseline: 1.5365x; 1.0439x over previous
#include <cuda_runtime.h>
#include <cuda_fp16.h>
#include <cstdint>

#define N_NODES 100000
#define DH 128          // feature dim (in = hid = out = 128)
#define NPB 8           // nodes per tile in gemm
#define E_MAX 2000000   // static CSR capacity (E = 1.6M in dataset)

// ---- packed f32x2 helpers (SASS FFMA2; PTX-only path) ----------------------
#define PACK2(d, lo, hi) \
    asm("mov.b64 %0, {%1, %2};" : "=l"(d) : "f"(lo), "f"(hi))
#define UNPACK2(lo, hi, v) \
    asm("mov.b64 {%0, %1}, %2;" : "=f"(lo), "=f"(hi) : "l"(v))
#define FMA2(d, a, b, c) \
    asm("fma.rn.f32x2 %0, %1, %2, %3;" : "=l"(d) : "l"(a), "l"(b), "l"(c))

// ---------------- scratch (static device globals; no runtime alloc) --------
__device__ float   g_agg[(size_t)N_NODES * DH];       // LN'd agg (GEMM input, fp32)
__device__ __half2 g_feath[(size_t)N_NODES * DH / 2]; // fp16 copy of input features
__device__ __half2 g_bufh[(size_t)N_NODES * DH / 2];  // fp16 inter-layer activations
__device__ int     g_cnt[N_NODES];
__device__ int     g_off[N_NODES + 1];
__device__ int     g_cur[N_NODES];
__device__ int     g_nbr[E_MAX];

// ---------------- CSR build ------------------------------------------------
__global__ void zero_cnt_kernel() {
    int i = blockIdx.x * blockDim.x + threadIdx.x;
    if (i < N_NODES) g_cnt[i] = 0;
}

__global__ void hist_kernel(const int* __restrict__ dst, int E) {
    int e = blockIdx.x * blockDim.x + threadIdx.x;
    if (e < E) atomicAdd(&g_cnt[__ldg(dst + e)], 1);
}

__global__ void scan_kernel() {
    __shared__ int part[1024];
    const int t = threadIdx.x;
    const int chunk = (N_NODES + 1023) / 1024;
    int b = t * chunk;
    int e = min(N_NODES, b + chunk);
    int s = 0;
    for (int i = b; i < e; i++) s += g_cnt[i];
    part[t] = s;
    __syncthreads();
    for (int o = 1; o < 1024; o <<= 1) {
        int v = (t >= o) ? part[t - o] : 0;
        __syncthreads();
        part[t] += v;
        __syncthreads();
    }
    int run = (t == 0) ? 0 : part[t - 1];
    for (int i = b; i < e; i++) {
        g_off[i] = run;
        g_cur[i] = run;
        run += g_cnt[i];
    }
    if (e == N_NODES) g_off[N_NODES] = run;
}

__global__ void fill_kernel(const int* __restrict__ src,
                            const int* __restrict__ dst, int E) {
    int e = blockIdx.x * blockDim.x + threadIdx.x;
    if (e < E) {
        int pos = atomicAdd(&g_cur[__ldg(dst + e)], 1);
        g_nbr[pos] = __ldg(src + e);
    }
}

// ---------------- features fp32 -> fp16 (once per call) --------------------
__global__ void conv_kernel(const float4* __restrict__ xin) {
    size_t idx = (size_t)blockIdx.x * blockDim.x + threadIdx.x;  // float4 index
    const size_t total = (size_t)N_NODES * (DH / 4);
    if (idx >= total) return;
    float4 v = __ldg(xin + idx);
    __half2 h0 = __floats2half2_rn(v.x, v.y);
    __half2 h1 = __floats2half2_rn(v.z, v.w);
    uint2 h;
    h.x = *(const unsigned*)&h0;
    h.y = *(const unsigned*)&h1;
    ((uint2*)g_feath)[idx] = h;
}

// ------ CSR gather (fp16 rows) + fused LayerNorm -> g_agg (fp32) -----------
// One warp per node; lane l owns halfs 4l..4l+3 (uint2 = 8B per lane, 256B/row).
__global__ __launch_bounds__(256)
void gather_ln_kernel(const uint2* __restrict__ xin,
                      const float* __restrict__ gamma,
                      const float* __restrict__ beta) {
    int node = (int)((blockIdx.x * (size_t)blockDim.x + threadIdx.x) >> 5);
    int lane = threadIdx.x & 31;
    if (node >= N_NODES) return;
    int i   = __ldg(&g_off[node]);
    int end = __ldg(&g_off[node + 1]);
    float4 acc = make_float4(0.f, 0.f, 0.f, 0.f);
    // 4-deep unroll for MLP (loads are only 8B/lane now)
    for (; i + 3 < end; i += 4) {
        int s0 = __ldg(g_nbr + i);
        int s1 = __ldg(g_nbr + i + 1);
        int s2 = __ldg(g_nbr + i + 2);
        int s3 = __ldg(g_nbr + i + 3);
        uint2 v0 = __ldg(xin + (size_t)s0 * (DH / 4) + lane);
        uint2 v1 = __ldg(xin + (size_t)s1 * (DH / 4) + lane);
        uint2 v2 = __ldg(xin + (size_t)s2 * (DH / 4) + lane);
        uint2 v3 = __ldg(xin + (size_t)s3 * (DH / 4) + lane);
        float2 a = __half22float2(*(const __half2*)&v0.x);
        float2 b = __half22float2(*(const __half2*)&v0.y);
        acc.x += a.x; acc.y += a.y; acc.z += b.x; acc.w += b.y;
        a = __half22float2(*(const __half2*)&v1.x);
        b = __half22float2(*(const __half2*)&v1.y);
        acc.x += a.x; acc.y += a.y; acc.z += b.x; acc.w += b.y;
        a = __half22float2(*(const __half2*)&v2.x);
        b = __half22float2(*(const __half2*)&v2.y);
        acc.x += a.x; acc.y += a.y; acc.z += b.x; acc.w += b.y;
        a = __half22float2(*(const __half2*)&v3.x);
        b = __half22float2(*(const __half2*)&v3.y);
        acc.x += a.x; acc.y += a.y; acc.z += b.x; acc.w += b.y;
    }
    for (; i < end; i++) {
        int s0 = __ldg(g_nbr + i);
        uint2 v0 = __ldg(xin + (size_t)s0 * (DH / 4) + lane);
        float2 a = __half22float2(*(const __half2*)&v0.x);
        float2 b = __half22float2(*(const __half2*)&v0.y);
        acc.x += a.x; acc.y += a.y; acc.z += b.x; acc.w += b.y;
    }
    // ---- LayerNorm over the row held by this warp ----
    float s  = acc.x + acc.y + acc.z + acc.w;
    float sq = acc.x*acc.x + acc.y*acc.y + acc.z*acc.z + acc.w*acc.w;
#pragma unroll
    for (int o = 16; o; o >>= 1) {
        s  += __shfl_xor_sync(0xFFFFFFFFu, s,  o);
        sq += __shfl_xor_sync(0xFFFFFFFFu, sq, o);
    }
    const float mu   = s * (1.0f / DH);
    const float var  = sq * (1.0f / DH) - mu * mu;
    const float rinv = rsqrtf(var + 1e-5f);
    float4 g4 = __ldg((const float4*)gamma + lane);
    float4 b4 = __ldg((const float4*)beta  + lane);
    float4 xn;
    xn.x = (acc.x - mu) * rinv * g4.x + b4.x;
    xn.y = (acc.y - mu) * rinv * g4.y + b4.y;
    xn.z = (acc.z - mu) * rinv * g4.z + b4.z;
    xn.w = (acc.w - mu) * rinv * g4.w + b4.w;
    ((float4*)g_agg)[(size_t)node * (DH / 4) + lane] = xn;
}

// ---------------- pure GEMM(100000x128 @ 128x128) + bias (+ReLU) -----------
// 256 threads = 8 K-groups (warp == K-group, 16 k each) x 32 col-groups
// (4 contiguous cols/thread as two f32x2 W pairs in registers).
// ReLU layers write fp16 activations to g_bufh; last layer writes fp32 out.
__global__ __launch_bounds__(256, 2)
void gemm_kernel(const float* __restrict__ W,
                 const float* __restrict__ bias,
                 float* __restrict__ out_f32, int relu) {
    __shared__ __align__(16) unsigned long long xdup[2][NPB][DH];  // 16 KB
    __shared__ __align__(16) float4 red4[8 * NPB * 32];            // 32 KB

    const int t  = threadIdx.x;
    const int kg = t >> 5;      // warp index == K-group (0..7)
    const int cg = t & 31;      // col group: cols cg*4 .. cg*4+3

    // W registers: two f32x2 pairs per k (16 k in this group)
    unsigned long long w01[16], w23[16];
#pragma unroll
    for (int kk = 0; kk < 16; kk++) {
        const float4 w4 = __ldg((const float4*)(W + (size_t)(kg * 16 + kk) * DH) + cg);
        PACK2(w01[kk], w4.x, w4.y);
        PACK2(w23[kk], w4.z, w4.w);
    }
    const float4 bias4 = __ldg((const float4*)bias + cg);

    const int nn_l = t >> 5;
    const int kq_l = t & 31;

    const int nTiles = N_NODES / NPB;       // 12500 exact
    int tile = blockIdx.x;
    float4 nxt = make_float4(0.f, 0.f, 0.f, 0.f);
    if (tile < nTiles)
        nxt = __ldg((const float4*)g_agg + (size_t)(tile * NPB + nn_l) * (DH / 4) + kq_l);

    int buf = 0;
    for (; tile < nTiles; tile += gridDim.x, buf ^= 1) {
        const int n0 = tile * NPB;

        // stage current tile (duplicated pairs), 2x STS.128 per thread
        {
            unsigned long long p0, p1, p2, p3;
            PACK2(p0, nxt.x, nxt.x);
            PACK2(p1, nxt.y, nxt.y);
            PACK2(p2, nxt.z, nxt.z);
            PACK2(p3, nxt.w, nxt.w);
            ulonglong2* xd = (ulonglong2*)&xdup[buf][nn_l][kq_l * 4];
            xd[0] = make_ulonglong2(p0, p1);
            xd[1] = make_ulonglong2(p2, p3);
        }
        __syncthreads();

        // prefetch next tile into registers (overlaps compute)
        const int tile2 = tile + gridDim.x;
        if (tile2 < nTiles)
            nxt = __ldg((const float4*)g_agg + (size_t)(tile2 * NPB + nn_l) * (DH / 4) + kq_l);

        // ---- compute: acc[nn] over this warp's 16 k values ----
        unsigned long long acc01[NPB], acc23[NPB];
        unsigned long long zero; PACK2(zero, 0.f, 0.f);
#pragma unroll
        for (int nn = 0; nn < NPB; nn++) { acc01[nn] = zero; acc23[nn] = zero; }

        const unsigned long long* xb = &xdup[buf][0][kg * 16];
#pragma unroll
        for (int kk = 0; kk < 16; kk++) {
            const unsigned long long a = w01[kk];
            const unsigned long long b = w23[kk];
#pragma unroll
            for (int nn = 0; nn < NPB; nn++) {
                const unsigned long long x2 = xb[nn * DH + kk];   // LDS.64 broadcast
                FMA2(acc01[nn], x2, a, acc01[nn]);
                FMA2(acc23[nn], x2, b, acc23[nn]);
            }
        }

        // ---- stage partials: red4[kg][nn][cg] ----
#pragma unroll
        for (int nn = 0; nn < NPB; nn++) {
            float a0, a1, a2, a3;
            UNPACK2(a0, a1, acc01[nn]);
            UNPACK2(a2, a3, acc23[nn]);
            red4[kg * (NPB * 32) + nn * 32 + cg] = make_float4(a0, a1, a2, a3);
        }
        __syncthreads();

        // ---- reduce over 8 K-groups: thread t owns output float4 #t ----
        {
            float4 sv = red4[t];
#pragma unroll
            for (int g = 1; g < 8; g++) {
                float4 r = red4[g * (NPB * 32) + t];
                sv.x += r.x; sv.y += r.y; sv.z += r.z; sv.w += r.w;
            }
            sv.x += bias4.x; sv.y += bias4.y; sv.z += bias4.z; sv.w += bias4.w;
            const size_t oidx = (size_t)(n0 + (t >> 5)) * (DH / 4) + (t & 31);
            if (relu) {
                sv.x = fmaxf(sv.x, 0.f); sv.y = fmaxf(sv.y, 0.f);
                sv.z = fmaxf(sv.z, 0.f); sv.w = fmaxf(sv.w, 0.f);
                __half2 h0 = __floats2half2_rn(sv.x, sv.y);
                __half2 h1 = __floats2half2_rn(sv.z, sv.w);
                uint2 h;
                h.x = *(const unsigned*)&h0;
                h.y = *(const unsigned*)&h1;
                ((uint2*)g_bufh)[oidx] = h;
            } else {
                ((float4*)out_f32)[oidx] = sv;
            }
        }
        // next iteration's first __syncthreads() orders red4 reuse
    }
}

// ---------------------------------------------------------------------------
extern "C" void kernel_launch(void* const* d_in, const int* in_sizes, int n_in,
                              void* d_out, int out_size) {
    const float* features = (const float*)d_in[0];
    const int*   src      = (const int*)d_in[1];
    const int*   dst      = (const int*)d_in[2];
    const float* g1 = (const float*)d_in[3];
    const float* be1= (const float*)d_in[4];
    const float* W1 = (const float*)d_in[5];
    const float* b1 = (const float*)d_in[6];
    const float* g2 = (const float*)d_in[7];
    const float* be2= (const float*)d_in[8];
    const float* W2 = (const float*)d_in[9];
    const float* b2 = (const float*)d_in[10];
    const float* g3 = (const float*)d_in[11];
    const float* be3= (const float*)d_in[12];
    const float* W3 = (const float*)d_in[13];
    const float* b3 = (const float*)d_in[14];
    float* out = (float*)d_out;

    const int E = in_sizes[1];

    // ---- CSR build + feature conversion (once per call) ----
    zero_cnt_kernel<<<(N_NODES + 255) / 256, 256>>>();
    hist_kernel<<<(E + 255) / 256, 256>>>(dst, E);
    scan_kernel<<<1, 1024>>>();
    fill_kernel<<<(E + 255) / 256, 256>>>(src, dst, E);
    conv_kernel<<<(N_NODES * (DH / 4) + 255) / 256, 256>>>((const float4*)features);

    // device-symbol addresses for gather input (half rows as uint2)
    const uint2* feath;
    const uint2* bufh;
    cudaGetSymbolAddress((void**)&feath, g_feath);
    cudaGetSymbolAddress((void**)&bufh,  g_bufh);

    const int gatherBlocks = (N_NODES * 32 + 255) / 256;   // warp per node
    const int gBlocks = 296;                               // persistent GEMM grid

    // ---- layer 1 ----
    gather_ln_kernel<<<gatherBlocks, 256>>>(feath, g1, be1);
    gemm_kernel<<<gBlocks, 256>>>(W1, b1, nullptr, 1);
    // ---- layer 2 ----
    gather_ln_kernel<<<gatherBlocks, 256>>>(bufh, g2, be2);
    gemm_kernel<<<gBlocks, 256>>>(W2, b2, nullptr, 1);
    // ---- layer 3 ----
    gather_ln_kernel<<<gatherBlocks, 256>>>(bufh, g3, be3);
    gemm_kernel<<<gBlocks, 256>>>(W3, b3, out, 0);
}